// round 13
// baseline (speedup 1.0000x reference)
#include <cuda_runtime.h>
#include <cuda_bf16.h>
#include <math.h>
#include <stdint.h>

// ---------------------------------------------------------------------------
// Model constants
// ---------------------------------------------------------------------------
#define SEQ      1024
#define DM       512
#define NHEAD    8
#define DH       64
#define NLAYER   12
#define DFF      2048
#define DEMB     768
#define CHUNK    128
#define NCHUNK   (SEQ / CHUNK)   // 8
#define EPS_ATTN 1e-6f
#define EPS_LN   1e-5f

// ---------------------------------------------------------------------------
// Scratch (no cudaMalloc allowed)
// ---------------------------------------------------------------------------
__device__ float g_embs[SEQ * DEMB];
__device__ float g_h   [SEQ * DM];     // fp32 residual stream
__device__ float g_hr  [SEQ * DM];     // tf32-rounded mirror (GEMM A input)
__device__ float g_q   [SEQ * DM];     // tf32-rounded
__device__ float g_k   [SEQ * DM];     // tf32-rounded
__device__ float g_v   [SEQ * DM];     // tf32-rounded
__device__ float g_attn[SEQ * DM];     // tf32-rounded
__device__ float g_oi  [SEQ * DM];     // intra-chunk attention out (fp32)
__device__ float g_ff  [SEQ * DFF];    // tf32-rounded
__device__ float g_KVch[NHEAD * NCHUNK * DH * DH];
__device__ float g_Kch [NHEAD * NCHUNK * DH];
__device__ float g_rs  [NHEAD * NCHUNK * CHUNK];
__device__ float g_hn  [SEQ * DM];

// tf32-rounded weight mirrors
__device__ float g_wq_r[NLAYER * DM * DM];
__device__ float g_wk_r[NLAYER * DM * DM];
__device__ float g_wv_r[NLAYER * DM * DM];
__device__ float g_wo_r[NLAYER * DM * DM];
__device__ float g_w1_r[NLAYER * DM * DFF];
__device__ float g_w2_r[NLAYER * DFF * DM];
__device__ float g_inw_r[DEMB * DM];

__device__ __forceinline__ uint32_t f2tf32(float x)
{
    uint32_t r;
    asm("cvt.rna.tf32.f32 %0, %1;" : "=r"(r) : "f"(x));
    return r;
}
__device__ __forceinline__ float tf32r(float x) { return __uint_as_float(f2tf32(x)); }

__device__ __forceinline__ void mma_tf32(float c[4], const uint32_t a[4], const uint32_t b[2])
{
    asm volatile(
        "mma.sync.aligned.m16n8k8.row.col.f32.tf32.tf32.f32 "
        "{%0,%1,%2,%3}, {%4,%5,%6,%7}, {%8,%9}, {%0,%1,%2,%3};\n"
        : "+f"(c[0]), "+f"(c[1]), "+f"(c[2]), "+f"(c[3])
        : "r"(a[0]), "r"(a[1]), "r"(a[2]), "r"(a[3]), "r"(b[0]), "r"(b[1]));
}

// ldmatrix x4: for tf32 data, one call delivers a full 16x8 A fragment
// (or two 8-col B tiles in n-major layout).
__device__ __forceinline__ void ldsm4(uint32_t& r0, uint32_t& r1, uint32_t& r2, uint32_t& r3,
                                      uint32_t addr)
{
    asm volatile("ldmatrix.sync.aligned.m8n8.x4.shared.b16 {%0,%1,%2,%3}, [%4];"
                 : "=r"(r0), "=r"(r1), "=r"(r2), "=r"(r3) : "r"(addr));
}

__device__ __forceinline__ void cp16(uint32_t dst, const void* src)
{
    asm volatile("cp.async.cg.shared.global [%0], [%1], 16;\n" :: "r"(dst), "l"(src));
}

// ---------------------------------------------------------------------------
// tf32 rounding pass (weights)
// ---------------------------------------------------------------------------
__global__ void round_tf32_kernel(const float4* __restrict__ s, float4* __restrict__ d, int n4)
{
    int i = blockIdx.x * blockDim.x + threadIdx.x;
    if (i >= n4) return;
    float4 v = s[i];
    v.x = tf32r(v.x); v.y = tf32r(v.y); v.z = tf32r(v.z); v.w = tf32r(v.w);
    d[i] = v;
}

// ---------------------------------------------------------------------------
// Embedding gather + scale (rounded: feeds in-proj GEMM A only)
// ---------------------------------------------------------------------------
__global__ void embed_kernel(const int* __restrict__ x,
                             const float* __restrict__ t0, const float* __restrict__ t1,
                             const float* __restrict__ t2, const float* __restrict__ t3,
                             const float* __restrict__ t4, const float* __restrict__ t5,
                             float* __restrict__ e)
{
    int idx = blockIdx.x * blockDim.x + threadIdx.x;
    if (idx >= SEQ * DEMB) return;
    int s = idx / DEMB, c = idx % DEMB;
    const float* tab; int off, sz, i; float sc;
    if      (c < 32)  { tab = t0; off = 0;   sz = 32;  i = 0; sc = 5.656854249492380f; }
    else if (c < 160) { tab = t1; off = 32;  sz = 128; i = 1; sc = 11.313708498984761f; }
    else if (c < 416) { tab = t2; off = 160; sz = 256; i = 2; sc = 16.0f; }
    else if (c < 672) { tab = t3; off = 416; sz = 256; i = 3; sc = 16.0f; }
    else if (c < 704) { tab = t4; off = 672; sz = 32;  i = 4; sc = 5.656854249492380f; }
    else              { tab = t5; off = 704; sz = 64;  i = 5; sc = 8.0f; }
    int xi = x[s * 6 + i];
    e[idx] = tf32r(tab[xi * sz + (c - off)] * sc);
}

// Positional encoding: h stays fp32; hr = rounded copy for GEMM A
__global__ void posenc_kernel(float* __restrict__ h, float* __restrict__ hr)
{
    int idx = blockIdx.x * blockDim.x + threadIdx.x;
    if (idx >= SEQ * DM) return;
    int s = idx >> 9, c = idx & 511;
    int i2 = c >> 1;
    float freq = expf((float)(2 * i2) * (-9.210340371976184f / 512.0f));
    float ang = (float)s * freq;
    float val = h[idx] + ((c & 1) ? cosf(ang) : sinf(ang));
    h[idx] = val;
    hr[idx] = tf32r(val);
}

// ---------------------------------------------------------------------------
// tf32 tensor-core GEMM, cp.async 4-stage pipeline, BK=32, ldmatrix A-frags.
// A and B buffers are both pre-rounded tf32 bit patterns.
// ---------------------------------------------------------------------------
#define TBM 64
#define TBN 64
#define TBK 32
#define NSTAGE 4
#define SMEM_GEMM ((NSTAGE * TBM * 36 + NSTAGE * TBK * 72) * 4)
enum { EPI_NONE = 0, EPI_PHI = 1, EPI_GELU = 2, EPI_RESID = 3, EPI_ROUND = 4 };

struct GemmOp { const float* B; const float* bias; float* C; int epi; };

__global__ __launch_bounds__(128) void mma_gemm_kernel(
    const float* __restrict__ A, GemmOp op0, GemmOp op1, GemmOp op2,
    int M, int N, int K)
{
    GemmOp op = (blockIdx.z == 0) ? op0 : (blockIdx.z == 1) ? op1 : op2;

    extern __shared__ float gsm[];
    float (*As)[TBM][36] = (float (*)[TBM][36])gsm;
    float (*Bs)[TBK][72] = (float (*)[TBK][72])(gsm + NSTAGE * TBM * 36);

    int tid  = threadIdx.x;
    int lane = tid & 31, wid = tid >> 5;
    int wr = wid >> 1, wc = wid & 1;
    int rowBase = blockIdx.y * TBM;
    int colBase = blockIdx.x * TBN;

    int ar0 = tid >> 3;
    int ak4 = (tid & 7) * 4;
    int bk0 = tid >> 4;
    int bn4 = (tid & 15) * 4;

    const float* Abase = A + (size_t)rowBase * K;
    const float* Bbase = op.B + colBase;

    int nk = K / TBK;

#pragma unroll
    for (int s = 0; s < NSTAGE - 1; s++) {
#pragma unroll
        for (int i = 0; i < 4; i++) {
            int arw = ar0 + 16 * i;
            int bkr = bk0 + 8 * i;
            cp16((uint32_t)__cvta_generic_to_shared(&As[s][arw][ak4]),
                 Abase + (size_t)arw * K + s * TBK + ak4);
            cp16((uint32_t)__cvta_generic_to_shared(&Bs[s][bkr][bn4]),
                 Bbase + (size_t)(s * TBK + bkr) * N + bn4);
        }
        asm volatile("cp.async.commit_group;");
    }

    float acc[2][4][4];
#pragma unroll
    for (int i = 0; i < 2; i++)
#pragma unroll
        for (int j = 0; j < 4; j++)
#pragma unroll
            for (int r = 0; r < 4; r++) acc[i][j][r] = 0.f;

    int ar = lane >> 2;
    int ac = lane & 3;
    // ldmatrix lane addressing for A fragments
    int lrow = (lane & 7) + ((lane >> 3) & 1) * 8;   // row offset within 16-row tile
    int lcol = (lane >> 4) * 4;                       // 0 or 4

    for (int kc = 0; kc < nk; kc++) {
        asm volatile("cp.async.wait_group %0;" :: "n"(NSTAGE - 2));
        __syncthreads();

        int buf = kc & (NSTAGE - 1);
        const float (*Asb)[36] = As[buf];
        const float (*Bsb)[72] = Bs[buf];
        uint32_t abase = (uint32_t)__cvta_generic_to_shared(&Asb[0][0]);

#pragma unroll
        for (int ks = 0; ks < 4; ks++) {
            uint32_t af[2][4], bf[4][2];
#pragma unroll
            for (int tm = 0; tm < 2; tm++) {
                int mb = wr * 32 + tm * 16;
                uint32_t addr = abase + (uint32_t)(((mb + lrow) * 36 + ks * 8 + lcol) * 4);
                ldsm4(af[tm][0], af[tm][1], af[tm][2], af[tm][3], addr);
            }
#pragma unroll
            for (int tn = 0; tn < 4; tn++) {
                int nb = wc * 32 + tn * 8 + ar;
                bf[tn][0] = __float_as_uint(Bsb[ks * 8 + ac][nb]);
                bf[tn][1] = __float_as_uint(Bsb[ks * 8 + 4 + ac][nb]);
            }
#pragma unroll
            for (int tm = 0; tm < 2; tm++)
#pragma unroll
                for (int tn = 0; tn < 4; tn++)
                    mma_tf32(acc[tm][tn], af[tm], bf[tn]);
        }

        int nxt = kc + NSTAGE - 1;
        if (nxt < nk) {
            int st = nxt & (NSTAGE - 1);
#pragma unroll
            for (int i = 0; i < 4; i++) {
                int arw = ar0 + 16 * i;
                int bkr = bk0 + 8 * i;
                cp16((uint32_t)__cvta_generic_to_shared(&As[st][arw][ak4]),
                     Abase + (size_t)arw * K + nxt * TBK + ak4);
                cp16((uint32_t)__cvta_generic_to_shared(&Bs[st][bkr][bn4]),
                     Bbase + (size_t)(nxt * TBK + bkr) * N + bn4);
            }
        }
        asm volatile("cp.async.commit_group;");
    }

    // epilogue
#pragma unroll
    for (int tmL = 0; tmL < 2; tmL++) {
        int row0 = rowBase + wr * 32 + tmL * 16 + (lane >> 2);
#pragma unroll
        for (int tn = 0; tn < 4; tn++) {
            int col = colBase + wc * 32 + tn * 8 + (lane & 3) * 2;
            float2 bb = *(const float2*)(op.bias + col);
            float* C0 = op.C + (size_t)row0 * N + col;
            float* C1 = C0 + (size_t)8 * N;
            float v0 = acc[tmL][tn][0] + bb.x;
            float v1 = acc[tmL][tn][1] + bb.y;
            float v2 = acc[tmL][tn][2] + bb.x;
            float v3 = acc[tmL][tn][3] + bb.y;
            if (op.epi == EPI_PHI) {
                v0 = tf32r((v0 > 0.f) ? v0 + 1.0f : expf(v0));
                v1 = tf32r((v1 > 0.f) ? v1 + 1.0f : expf(v1));
                v2 = tf32r((v2 > 0.f) ? v2 + 1.0f : expf(v2));
                v3 = tf32r((v3 > 0.f) ? v3 + 1.0f : expf(v3));
            } else if (op.epi == EPI_GELU) {
                v0 = tf32r(0.5f * v0 * (1.0f + erff(v0 * 0.7071067811865475f)));
                v1 = tf32r(0.5f * v1 * (1.0f + erff(v1 * 0.7071067811865475f)));
                v2 = tf32r(0.5f * v2 * (1.0f + erff(v2 * 0.7071067811865475f)));
                v3 = tf32r(0.5f * v3 * (1.0f + erff(v3 * 0.7071067811865475f)));
            } else if (op.epi == EPI_RESID) {
                float2 o0 = *(const float2*)C0;
                float2 o1 = *(const float2*)C1;
                v0 += o0.x; v1 += o0.y; v2 += o1.x; v3 += o1.y;
            } else if (op.epi == EPI_ROUND) {
                v0 = tf32r(v0); v1 = tf32r(v1); v2 = tf32r(v2); v3 = tf32r(v3);
            }
            float2 r0 = {v0, v1}, r1 = {v2, v3};
            *(float2*)C0 = r0;
            *(float2*)C1 = r1;
        }
    }
}

// ---------------------------------------------------------------------------
// Fused attention A (q,k,v pre-rounded tf32):
//   S = mask(q k^T) (smem, rounded) + rowsums ; out_intra = S@v ; KV = k^T v
// ---------------------------------------------------------------------------
#define SMEM_ATTA ((3 * 128 * 68 + 128 * 132 + 128 * 4) * 4)

__global__ __launch_bounds__(256) void attn_a_kernel(
    const float* __restrict__ q, const float* __restrict__ k, const float* __restrict__ v,
    float* __restrict__ oi, float* __restrict__ rsg,
    float* __restrict__ KVch, float* __restrict__ Kch)
{
    extern __shared__ float sm[];
    float* qs  = sm;                        // [128][68]
    float* kn  = qs + 128 * 68;             // [128][68]
    float* vs  = kn + 128 * 68;             // [128][68]
    float* Ss  = vs + 128 * 68;             // [128][132] / later kT[64][132]
    float* rs2 = Ss + 128 * 132;            // [128][4]

    int c  = blockIdx.x;
    int hd = blockIdx.y;
    int tid = threadIdx.x;
    int lane = tid & 31, wid = tid >> 5;
    int wr = wid >> 2, wc = wid & 3;

    int lrow = (lane & 7) + ((lane >> 3) & 1) * 8;
    int lcol = (lane >> 4) * 4;
    // B-side (n-major) ldmatrix lane mapping
    int bnr = ((lane >> 4) * 8) + (lane & 7);   // n-row offset within 16-n supertile
    int bkc = ((lane >> 3) & 1) * 4;            // k offset 0/4

    uint32_t qsb = (uint32_t)__cvta_generic_to_shared(qs);
    uint32_t knb = (uint32_t)__cvta_generic_to_shared(kn);
    uint32_t ssb = (uint32_t)__cvta_generic_to_shared(Ss);

    {
        int r = tid >> 1;
        int dbase = (tid & 1) * 32;
        const float* gq = q + (size_t)(c * CHUNK + r) * DM + hd * DH + dbase;
        const float* gk = k + (size_t)(c * CHUNK + r) * DM + hd * DH + dbase;
        const float* gv = v + (size_t)(c * CHUNK + r) * DM + hd * DH + dbase;
#pragma unroll
        for (int j = 0; j < 8; j++) {
            int d = dbase + j * 4;
            *(float4*)&qs[r * 68 + d] = *(const float4*)(gq + j * 4);
            *(float4*)&kn[r * 68 + d] = *(const float4*)(gk + j * 4);
            *(float4*)&vs[r * 68 + d] = *(const float4*)(gv + j * 4);
        }
    }
    __syncthreads();

    // ---- S phase: warp tile 64x32, K=64 ----
    {
        float acc[4][4][4];
#pragma unroll
        for (int i = 0; i < 4; i++)
#pragma unroll
            for (int j = 0; j < 4; j++)
#pragma unroll
                for (int r = 0; r < 4; r++) acc[i][j][r] = 0.f;

#pragma unroll
        for (int ks = 0; ks < 8; ks++) {
            uint32_t af[4][4], bf[4][2];
#pragma unroll
            for (int tm = 0; tm < 4; tm++) {
                int mb = wr * 64 + tm * 16;
                ldsm4(af[tm][0], af[tm][1], af[tm][2], af[tm][3],
                      qsb + (uint32_t)(((mb + lrow) * 68 + ks * 8 + lcol) * 4));
            }
#pragma unroll
            for (int pair = 0; pair < 2; pair++) {
                int nb0 = wc * 32 + pair * 16;
                ldsm4(bf[pair * 2][0], bf[pair * 2][1], bf[pair * 2 + 1][0], bf[pair * 2 + 1][1],
                      knb + (uint32_t)(((nb0 + bnr) * 68 + ks * 8 + bkc) * 4));
            }
#pragma unroll
            for (int tm = 0; tm < 4; tm++)
#pragma unroll
                for (int tn = 0; tn < 4; tn++)
                    mma_tf32(acc[tm][tn], af[tm], bf[tn]);
        }

        // mask + rowsums + rounded store to smem
#pragma unroll
        for (int tm = 0; tm < 4; tm++) {
            int row0 = wr * 64 + tm * 16 + (lane >> 2);
            int row1 = row0 + 8;
            float p0 = 0.f, p1 = 0.f;
#pragma unroll
            for (int tn = 0; tn < 4; tn++) {
                int col = wc * 32 + tn * 8 + (lane & 3) * 2;
                float2 r0, r1;
                r0.x = (col     <= row0) ? acc[tm][tn][0] : 0.f;
                r0.y = (col + 1 <= row0) ? acc[tm][tn][1] : 0.f;
                r1.x = (col     <= row1) ? acc[tm][tn][2] : 0.f;
                r1.y = (col + 1 <= row1) ? acc[tm][tn][3] : 0.f;
                p0 += r0.x + r0.y;
                p1 += r1.x + r1.y;
                r0.x = tf32r(r0.x); r0.y = tf32r(r0.y);
                r1.x = tf32r(r1.x); r1.y = tf32r(r1.y);
                *(float2*)&Ss[row0 * 132 + col] = r0;
                *(float2*)&Ss[row1 * 132 + col] = r1;
            }
#pragma unroll
            for (int o = 1; o < 4; o <<= 1) {
                p0 += __shfl_xor_sync(0xffffffffu, p0, o);
                p1 += __shfl_xor_sync(0xffffffffu, p1, o);
            }
            if ((lane & 3) == 0) {
                rs2[row0 * 4 + wc] = p0;
                rs2[row1 * 4 + wc] = p1;
            }
        }
    }
    __syncthreads();

    if (tid < CHUNK) {
        rsg[(hd * NCHUNK + c) * CHUNK + tid] =
            rs2[tid * 4 + 0] + rs2[tid * 4 + 1] + rs2[tid * 4 + 2] + rs2[tid * 4 + 3];
    }

    // ---- out_intra = S @ v : warp tile 64x16, K=128 ----
    {
        float acc[4][2][4];
#pragma unroll
        for (int i = 0; i < 4; i++)
#pragma unroll
            for (int j = 0; j < 2; j++)
#pragma unroll
                for (int r = 0; r < 4; r++) acc[i][j][r] = 0.f;

#pragma unroll
        for (int ks = 0; ks < 16; ks++) {
            uint32_t af[4][4], bf[2][2];
#pragma unroll
            for (int tm = 0; tm < 4; tm++) {
                int mb = wr * 64 + tm * 16;
                ldsm4(af[tm][0], af[tm][1], af[tm][2], af[tm][3],
                      ssb + (uint32_t)(((mb + lrow) * 132 + ks * 8 + lcol) * 4));
            }
#pragma unroll
            for (int tn = 0; tn < 2; tn++) {
                int nb = wc * 16 + tn * 8 + (lane >> 2);
                bf[tn][0] = __float_as_uint(vs[(ks * 8 + (lane & 3)) * 68 + nb]);
                bf[tn][1] = __float_as_uint(vs[(ks * 8 + 4 + (lane & 3)) * 68 + nb]);
            }
#pragma unroll
            for (int tm = 0; tm < 4; tm++)
#pragma unroll
                for (int tn = 0; tn < 2; tn++)
                    mma_tf32(acc[tm][tn], af[tm], bf[tn]);
        }

#pragma unroll
        for (int tm = 0; tm < 4; tm++) {
            int s0 = wr * 64 + tm * 16 + (lane >> 2);
            int s1 = s0 + 8;
#pragma unroll
            for (int tn = 0; tn < 2; tn++) {
                int e = wc * 16 + tn * 8 + (lane & 3) * 2;
                float2 r0 = {acc[tm][tn][0], acc[tm][tn][1]};
                float2 r1 = {acc[tm][tn][2], acc[tm][tn][3]};
                *(float2*)&oi[(size_t)(c * CHUNK + s0) * DM + hd * DH + e] = r0;
                *(float2*)&oi[(size_t)(c * CHUNK + s1) * DM + hd * DH + e] = r1;
            }
        }
    }
    __syncthreads();

    // ---- build kT[64][132] into Ss region (values already tf32) ----
    for (int idx = tid; idx < CHUNK * DH; idx += 256) {
        int r = idx >> 6, d = idx & 63;
        Ss[d * 132 + r] = kn[r * 68 + d];
    }
    __syncthreads();

    // ---- KV = k^T v : warp tile 32x16, K=128 ----
    {
        float acc[2][2][4];
#pragma unroll
        for (int i = 0; i < 2; i++)
#pragma unroll
            for (int j = 0; j < 2; j++)
#pragma unroll
                for (int r = 0; r < 4; r++) acc[i][j][r] = 0.f;

#pragma unroll
        for (int ks = 0; ks < 16; ks++) {
            uint32_t af[2][4], bf[2][2];
#pragma unroll
            for (int tm = 0; tm < 2; tm++) {
                int mb = wr * 32 + tm * 16;
                ldsm4(af[tm][0], af[tm][1], af[tm][2], af[tm][3],
                      ssb + (uint32_t)(((mb + lrow) * 132 + ks * 8 + lcol) * 4));
            }
#pragma unroll
            for (int tn = 0; tn < 2; tn++) {
                int nb = wc * 16 + tn * 8 + (lane >> 2);
                bf[tn][0] = __float_as_uint(vs[(ks * 8 + (lane & 3)) * 68 + nb]);
                bf[tn][1] = __float_as_uint(vs[(ks * 8 + 4 + (lane & 3)) * 68 + nb]);
            }
#pragma unroll
            for (int tm = 0; tm < 2; tm++)
#pragma unroll
                for (int tn = 0; tn < 2; tn++)
                    mma_tf32(acc[tm][tn], af[tm], bf[tn]);
        }

        float* KVo = KVch + (size_t)(hd * NCHUNK + c) * (DH * DH);
#pragma unroll
        for (int tm = 0; tm < 2; tm++) {
            int d0 = wr * 32 + tm * 16 + (lane >> 2);
            int d1 = d0 + 8;
#pragma unroll
            for (int tn = 0; tn < 2; tn++) {
                int e = wc * 16 + tn * 8 + (lane & 3) * 2;
                float2 r0 = {acc[tm][tn][0], acc[tm][tn][1]};
                float2 r1 = {acc[tm][tn][2], acc[tm][tn][3]};
                *(float2*)&KVo[d0 * DH + e] = r0;
                *(float2*)&KVo[d1 * DH + e] = r1;
            }
        }
    }

    if (tid < DH) {
        float s = 0.f;
        for (int t = 0; t < CHUNK; t++) s += kn[t * 68 + tid];
        Kch[(hd * NCHUNK + c) * DH + tid] = s;
    }
}

// ---------------------------------------------------------------------------
// Fused attention B: inline scan + z + out = z * (oi + q @ kvcarry)
// ---------------------------------------------------------------------------
#define SMEM_ATTB ((128 * 68 + 64 * 68 + 64 + 128) * 4)

__global__ __launch_bounds__(256) void attn_b_kernel(
    const float* __restrict__ q, const float* __restrict__ oi, const float* __restrict__ rsg,
    const float* __restrict__ KVch, const float* __restrict__ Kch, float* __restrict__ out)
{
    extern __shared__ float sm[];
    float* qs = sm;                 // [128][68]
    float* kv = qs + 128 * 68;      // [64][68]
    float* kc = kv + 64 * 68;       // [64]
    float* zz = kc + 64;            // [128]

    int c  = blockIdx.x;
    int hd = blockIdx.y;
    int tid = threadIdx.x;
    int lane = tid & 31, wid = tid >> 5;
    int wr = wid >> 2, wc = wid & 3;

    int lrow = (lane & 7) + ((lane >> 3) & 1) * 8;
    int lcol = (lane >> 4) * 4;
    uint32_t qsb = (uint32_t)__cvta_generic_to_shared(qs);

    {
        int r = tid >> 1;
        int eb = (tid & 1) * 32;
        const float* gq = q + (size_t)(c * CHUNK + r) * DM + hd * DH + eb;
#pragma unroll
        for (int j = 0; j < 8; j++)
            *(float4*)&qs[r * 68 + eb + j * 4] = *(const float4*)(gq + j * 4);
    }
    for (int i = tid; i < DH * DH; i += 256) {
        float s = 0.f;
        for (int cc = 0; cc < c; cc++)
            s += KVch[(size_t)(hd * NCHUNK + cc) * (DH * DH) + i];
        kv[(i >> 6) * 68 + (i & 63)] = tf32r(s);
    }
    if (tid < DH) {
        float s = 0.f;
        for (int cc = 0; cc < c; cc++)
            s += Kch[(hd * NCHUNK + cc) * DH + tid];
        kc[tid] = s;
    }
    __syncthreads();

    if (tid < CHUNK) {
        float zr = rsg[(hd * NCHUNK + c) * CHUNK + tid];
        for (int d = 0; d < DH; d++) zr = fmaf(qs[tid * 68 + d], kc[d], zr);
        zz[tid] = 1.0f / (zr + EPS_ATTN);
    }
    __syncthreads();

    float acc[4][2][4];
#pragma unroll
    for (int i = 0; i < 4; i++)
#pragma unroll
        for (int j = 0; j < 2; j++)
#pragma unroll
            for (int r = 0; r < 4; r++) acc[i][j][r] = 0.f;

#pragma unroll
    for (int ks = 0; ks < 8; ks++) {
        uint32_t af[4][4], bf[2][2];
#pragma unroll
        for (int tm = 0; tm < 4; tm++) {
            int mb = wr * 64 + tm * 16;
            ldsm4(af[tm][0], af[tm][1], af[tm][2], af[tm][3],
                  qsb + (uint32_t)(((mb + lrow) * 68 + ks * 8 + lcol) * 4));
        }
#pragma unroll
        for (int tn = 0; tn < 2; tn++) {
            int nb = wc * 16 + tn * 8 + (lane >> 2);
            bf[tn][0] = __float_as_uint(kv[(ks * 8 + (lane & 3)) * 68 + nb]);
            bf[tn][1] = __float_as_uint(kv[(ks * 8 + 4 + (lane & 3)) * 68 + nb]);
        }
#pragma unroll
        for (int tm = 0; tm < 4; tm++)
#pragma unroll
            for (int tn = 0; tn < 2; tn++)
                mma_tf32(acc[tm][tn], af[tm], bf[tn]);
    }

#pragma unroll
    for (int tm = 0; tm < 4; tm++) {
        int s0 = wr * 64 + tm * 16 + (lane >> 2);
        int s1 = s0 + 8;
        float z0 = zz[s0], z1 = zz[s1];
#pragma unroll
        for (int tn = 0; tn < 2; tn++) {
            int e = wc * 16 + tn * 8 + (lane & 3) * 2;
            size_t o0 = (size_t)(c * CHUNK + s0) * DM + hd * DH + e;
            size_t o1 = (size_t)(c * CHUNK + s1) * DM + hd * DH + e;
            float2 i0 = *(const float2*)&oi[o0];
            float2 i1 = *(const float2*)&oi[o1];
            float2 r0 = {tf32r(z0 * (i0.x + acc[tm][tn][0])), tf32r(z0 * (i0.y + acc[tm][tn][1]))};
            float2 r1 = {tf32r(z1 * (i1.x + acc[tm][tn][2])), tf32r(z1 * (i1.y + acc[tm][tn][3]))};
            *(float2*)&out[o0] = r0;
            *(float2*)&out[o1] = r1;
        }
    }
}

// ---------------------------------------------------------------------------
// LayerNorm: warp per row, 8 rows/block; dual output (fp32 + rounded mirror)
// ---------------------------------------------------------------------------
__global__ __launch_bounds__(256) void ln_kernel(
    const float* __restrict__ src, float* __restrict__ dst, float* __restrict__ dstr,
    const float* __restrict__ g, const float* __restrict__ b)
{
    int row = blockIdx.x * 8 + (threadIdx.x >> 5);
    int lane = threadIdx.x & 31;
    const float* sr = src + (size_t)row * DM + lane * 16;
    float4 v[4];
    float sum = 0.f, sq = 0.f;
#pragma unroll
    for (int i = 0; i < 4; i++) {
        v[i] = *(const float4*)(sr + i * 4);
        sum += v[i].x + v[i].y + v[i].z + v[i].w;
        sq  += v[i].x * v[i].x + v[i].y * v[i].y + v[i].z * v[i].z + v[i].w * v[i].w;
    }
#pragma unroll
    for (int o = 16; o > 0; o >>= 1) {
        sum += __shfl_xor_sync(0xffffffffu, sum, o);
        sq  += __shfl_xor_sync(0xffffffffu, sq,  o);
    }
    float mean = sum * (1.0f / DM);
    float var  = sq * (1.0f / DM) - mean * mean;
    float r = rsqrtf(var + EPS_LN);
    float* dr = dst + (size_t)row * DM + lane * 16;
#pragma unroll
    for (int i = 0; i < 4; i++) {
        float4 gg = *(const float4*)(g + lane * 16 + i * 4);
        float4 bb = *(const float4*)(b + lane * 16 + i * 4);
        float4 o;
        o.x = (v[i].x - mean) * r * gg.x + bb.x;
        o.y = (v[i].y - mean) * r * gg.y + bb.y;
        o.z = (v[i].z - mean) * r * gg.z + bb.z;
        o.w = (v[i].w - mean) * r * gg.w + bb.w;
        *(float4*)(dr + i * 4) = o;
        if (dstr) {
            float4 q;
            q.x = tf32r(o.x); q.y = tf32r(o.y); q.z = tf32r(o.z); q.w = tf32r(o.w);
            *(float4*)(dstr + (size_t)row * DM + lane * 16 + i * 4) = q;
        }
    }
}

// ---------------------------------------------------------------------------
// Emotion projection
// ---------------------------------------------------------------------------
__global__ __launch_bounds__(256) void emo_kernel(
    const float* __restrict__ hn, const float* __restrict__ W,
    const float* __restrict__ bias, float* __restrict__ out)
{
    int s = blockIdx.x;
    int w = threadIdx.x >> 5, lane = threadIdx.x & 31;
    float acc = 0.f;
    const float* hr = hn + (size_t)s * DM;
    for (int d = lane; d < DM; d += 32)
        acc = fmaf(hr[d], W[d * 8 + w], acc);
#pragma unroll
    for (int o = 16; o > 0; o >>= 1) acc += __shfl_xor_sync(0xffffffffu, acc, o);
    if (lane == 0) out[s * 8 + w] = acc + bias[w];
}

// ---------------------------------------------------------------------------
// Host launch
// ---------------------------------------------------------------------------
template <typename T>
static float* symptr(T& sym)
{
    void* p = nullptr;
    cudaGetSymbolAddress(&p, sym);
    return (float*)p;
}

extern "C" void kernel_launch(void* const* d_in, const int* in_sizes, int n_in,
                              void* d_out, int out_size)
{
    const int*   x        = (const int*)  d_in[0];
    const float* emb_bar  = (const float*)d_in[1];
    const float* emb_pos  = (const float*)d_in[2];
    const float* emb_pit  = (const float*)d_in[3];
    const float* emb_dur  = (const float*)d_in[4];
    const float* emb_typ  = (const float*)d_in[5];
    const float* emb_emo  = (const float*)d_in[6];
    const float* in_w     = (const float*)d_in[7];
    const float* in_b     = (const float*)d_in[8];
    const float* wq       = (const float*)d_in[9];
    const float* bq       = (const float*)d_in[10];
    const float* wk       = (const float*)d_in[11];
    const float* bk       = (const float*)d_in[12];
    const float* wv       = (const float*)d_in[13];
    const float* bv       = (const float*)d_in[14];
    const float* wo       = (const float*)d_in[15];
    const float* bo       = (const float*)d_in[16];
    const float* ln1_g    = (const float*)d_in[17];
    const float* ln1_b    = (const float*)d_in[18];
    const float* w1       = (const float*)d_in[19];
    const float* b1       = (const float*)d_in[20];
    const float* w2       = (const float*)d_in[21];
    const float* b2       = (const float*)d_in[22];
    const float* ln2_g    = (const float*)d_in[23];
    const float* ln2_b    = (const float*)d_in[24];
    const float* lnf_g    = (const float*)d_in[25];
    const float* lnf_b    = (const float*)d_in[26];
    const float* proj_w   = (const float*)d_in[27];
    const float* proj_b   = (const float*)d_in[28];

    float* embs = symptr(g_embs);
    float* h    = symptr(g_h);
    float* hr   = symptr(g_hr);
    float* q    = symptr(g_q);
    float* k    = symptr(g_k);
    float* v    = symptr(g_v);
    float* attn = symptr(g_attn);
    float* oi   = symptr(g_oi);
    float* ff   = symptr(g_ff);
    float* KVch = symptr(g_KVch);
    float* Kch  = symptr(g_Kch);
    float* rsg  = symptr(g_rs);
    float* hn   = symptr(g_hn);

    float* wq_r  = symptr(g_wq_r);
    float* wk_r  = symptr(g_wk_r);
    float* wv_r  = symptr(g_wv_r);
    float* wo_r  = symptr(g_wo_r);
    float* w1_r  = symptr(g_w1_r);
    float* w2_r  = symptr(g_w2_r);
    float* inw_r = symptr(g_inw_r);

    cudaFuncSetAttribute(mma_gemm_kernel, cudaFuncAttributeMaxDynamicSharedMemorySize, SMEM_GEMM);
    cudaFuncSetAttribute(attn_a_kernel,   cudaFuncAttributeMaxDynamicSharedMemorySize, SMEM_ATTA);
    cudaFuncSetAttribute(attn_b_kernel,   cudaFuncAttributeMaxDynamicSharedMemorySize, SMEM_ATTB);

    // --- weight pre-rounding to tf32 ---
    {
        const int T = 256;
        int n4;
        n4 = DEMB * DM / 4;
        round_tf32_kernel<<<(n4 + T - 1) / T, T>>>((const float4*)in_w, (float4*)inw_r, n4);
        n4 = NLAYER * DM * DM / 4;
        round_tf32_kernel<<<(n4 + T - 1) / T, T>>>((const float4*)wq, (float4*)wq_r, n4);
        round_tf32_kernel<<<(n4 + T - 1) / T, T>>>((const float4*)wk, (float4*)wk_r, n4);
        round_tf32_kernel<<<(n4 + T - 1) / T, T>>>((const float4*)wv, (float4*)wv_r, n4);
        round_tf32_kernel<<<(n4 + T - 1) / T, T>>>((const float4*)wo, (float4*)wo_r, n4);
        n4 = NLAYER * DM * DFF / 4;
        round_tf32_kernel<<<(n4 + T - 1) / T, T>>>((const float4*)w1, (float4*)w1_r, n4);
        round_tf32_kernel<<<(n4 + T - 1) / T, T>>>((const float4*)w2, (float4*)w2_r, n4);
    }

    // Embedding + input projection + positional encoding
    embed_kernel<<<(SEQ * DEMB + 255) / 256, 256>>>(x, emb_bar, emb_pos, emb_pit,
                                                    emb_dur, emb_typ, emb_emo, embs);
    {
        GemmOp op{inw_r, in_b, h, EPI_NONE};
        mma_gemm_kernel<<<dim3(DM / TBN, SEQ / TBM, 1), 128, SMEM_GEMM>>>(embs, op, op, op, SEQ, DM, DEMB);
    }
    posenc_kernel<<<(SEQ * DM + 255) / 256, 256>>>(h, hr);

    for (int l = 0; l < NLAYER; l++) {
        const float* wq_l = wq_r + (size_t)l * DM * DM;
        const float* wk_l = wk_r + (size_t)l * DM * DM;
        const float* wv_l = wv_r + (size_t)l * DM * DM;
        const float* wo_l = wo_r + (size_t)l * DM * DM;
        const float* w1_l = w1_r + (size_t)l * DM * DFF;
        const float* w2_l = w2_r + (size_t)l * DFF * DM;

        GemmOp oq{wq_l, bq + l * DM, q, EPI_PHI};
        GemmOp ok{wk_l, bk + l * DM, k, EPI_PHI};
        GemmOp ov{wv_l, bv + l * DM, v, EPI_ROUND};
        mma_gemm_kernel<<<dim3(DM / TBN, SEQ / TBM, 3), 128, SMEM_GEMM>>>(hr, oq, ok, ov, SEQ, DM, DM);

        attn_a_kernel<<<dim3(NCHUNK, NHEAD), 256, SMEM_ATTA>>>(q, k, v, oi, rsg, KVch, Kch);
        attn_b_kernel<<<dim3(NCHUNK, NHEAD), 256, SMEM_ATTB>>>(q, oi, rsg, KVch, Kch, attn);

        GemmOp oo{wo_l, bo + l * DM, h, EPI_RESID};
        mma_gemm_kernel<<<dim3(DM / TBN, SEQ / TBM, 1), 128, SMEM_GEMM>>>(attn, oo, oo, oo, SEQ, DM, DM);
        ln_kernel<<<SEQ / 8, 256>>>(h, h, hr, ln1_g + l * DM, ln1_b + l * DM);

        GemmOp of1{w1_l, b1 + l * DFF, ff, EPI_GELU};
        mma_gemm_kernel<<<dim3(DFF / TBN, SEQ / TBM, 1), 128, SMEM_GEMM>>>(hr, of1, of1, of1, SEQ, DFF, DM);
        GemmOp of2{w2_l, b2 + l * DM, h, EPI_RESID};
        mma_gemm_kernel<<<dim3(DM / TBN, SEQ / TBM, 1), 128, SMEM_GEMM>>>(ff, of2, of2, of2, SEQ, DM, DFF);
        ln_kernel<<<SEQ / 8, 256>>>(h, h, hr, ln2_g + l * DM, ln2_b + l * DM);
    }

    // Final norm + outputs
    float* o = (float*)d_out;
    float* hdst;
    float* edst;
    const int H_ELEMS = SEQ * DM;
    const int E_ELEMS = SEQ * 8;
    if (out_size >= H_ELEMS + E_ELEMS)      { hdst = o;  edst = o + H_ELEMS; }
    else if (out_size >= H_ELEMS)           { hdst = o;  edst = hn; }
    else                                    { hdst = hn; edst = o; }

    ln_kernel<<<SEQ / 8, 256>>>(h, hdst, nullptr, lnf_g, lnf_b);
    emo_kernel<<<SEQ, 256>>>(hdst, proj_w, proj_b, edst);
}

// round 14
// speedup vs baseline: 1.0045x; 1.0045x over previous
#include <cuda_runtime.h>
#include <cuda_bf16.h>
#include <math.h>
#include <stdint.h>

// ---------------------------------------------------------------------------
// Model constants
// ---------------------------------------------------------------------------
#define SEQ      1024
#define DM       512
#define NHEAD    8
#define DH       64
#define NLAYER   12
#define DFF      2048
#define DEMB     768
#define CHUNK    128
#define NCHUNK   (SEQ / CHUNK)   // 8
#define EPS_ATTN 1e-6f
#define EPS_LN   1e-5f

// ---------------------------------------------------------------------------
// Scratch (no cudaMalloc allowed)
// ---------------------------------------------------------------------------
__device__ float g_embs[SEQ * DEMB];
__device__ float g_h   [SEQ * DM];     // fp32 residual stream
__device__ float g_hr  [SEQ * DM];     // tf32-rounded mirror (GEMM A input)
__device__ float g_q   [SEQ * DM];     // tf32-rounded
__device__ float g_k   [SEQ * DM];     // tf32-rounded
__device__ float g_v   [SEQ * DM];     // tf32-rounded
__device__ float g_attn[SEQ * DM];     // tf32-rounded
__device__ float g_oi  [SEQ * DM];     // intra-chunk attention out (fp32)
__device__ float g_ff  [SEQ * DFF];    // tf32-rounded
__device__ float g_KVch[NHEAD * NCHUNK * DH * DH];
__device__ float g_Kch [NHEAD * NCHUNK * DH];
__device__ float g_rs  [NHEAD * NCHUNK * CHUNK];
__device__ float g_hn  [SEQ * DM];

// tf32-rounded weight mirrors
__device__ float g_wq_r[NLAYER * DM * DM];
__device__ float g_wk_r[NLAYER * DM * DM];
__device__ float g_wv_r[NLAYER * DM * DM];
__device__ float g_wo_r[NLAYER * DM * DM];
__device__ float g_w1_r[NLAYER * DM * DFF];
__device__ float g_w2_r[NLAYER * DFF * DM];
__device__ float g_inw_r[DEMB * DM];

__device__ __forceinline__ uint32_t f2tf32(float x)
{
    uint32_t r;
    asm("cvt.rna.tf32.f32 %0, %1;" : "=r"(r) : "f"(x));
    return r;
}
__device__ __forceinline__ float tf32r(float x) { return __uint_as_float(f2tf32(x)); }

__device__ __forceinline__ void mma_tf32(float c[4], const uint32_t a[4], const uint32_t b[2])
{
    asm volatile(
        "mma.sync.aligned.m16n8k8.row.col.f32.tf32.tf32.f32 "
        "{%0,%1,%2,%3}, {%4,%5,%6,%7}, {%8,%9}, {%0,%1,%2,%3};\n"
        : "+f"(c[0]), "+f"(c[1]), "+f"(c[2]), "+f"(c[3])
        : "r"(a[0]), "r"(a[1]), "r"(a[2]), "r"(a[3]), "r"(b[0]), "r"(b[1]));
}

// ldmatrix x4: for tf32 data, one call delivers a full 16x8 A fragment
// (or two 8-col B tiles in n-major layout).
__device__ __forceinline__ void ldsm4(uint32_t& r0, uint32_t& r1, uint32_t& r2, uint32_t& r3,
                                      uint32_t addr)
{
    asm volatile("ldmatrix.sync.aligned.m8n8.x4.shared.b16 {%0,%1,%2,%3}, [%4];"
                 : "=r"(r0), "=r"(r1), "=r"(r2), "=r"(r3) : "r"(addr));
}

__device__ __forceinline__ void cp16(uint32_t dst, const void* src)
{
    asm volatile("cp.async.cg.shared.global [%0], [%1], 16;\n" :: "r"(dst), "l"(src));
}

// ---------------------------------------------------------------------------
// tf32 rounding pass (weights)
// ---------------------------------------------------------------------------
__global__ void round_tf32_kernel(const float4* __restrict__ s, float4* __restrict__ d, int n4)
{
    int i = blockIdx.x * blockDim.x + threadIdx.x;
    if (i >= n4) return;
    float4 v = s[i];
    v.x = tf32r(v.x); v.y = tf32r(v.y); v.z = tf32r(v.z); v.w = tf32r(v.w);
    d[i] = v;
}

// ---------------------------------------------------------------------------
// Embedding gather + scale (rounded: feeds in-proj GEMM A only)
// ---------------------------------------------------------------------------
__global__ void embed_kernel(const int* __restrict__ x,
                             const float* __restrict__ t0, const float* __restrict__ t1,
                             const float* __restrict__ t2, const float* __restrict__ t3,
                             const float* __restrict__ t4, const float* __restrict__ t5,
                             float* __restrict__ e)
{
    int idx = blockIdx.x * blockDim.x + threadIdx.x;
    if (idx >= SEQ * DEMB) return;
    int s = idx / DEMB, c = idx % DEMB;
    const float* tab; int off, sz, i; float sc;
    if      (c < 32)  { tab = t0; off = 0;   sz = 32;  i = 0; sc = 5.656854249492380f; }
    else if (c < 160) { tab = t1; off = 32;  sz = 128; i = 1; sc = 11.313708498984761f; }
    else if (c < 416) { tab = t2; off = 160; sz = 256; i = 2; sc = 16.0f; }
    else if (c < 672) { tab = t3; off = 416; sz = 256; i = 3; sc = 16.0f; }
    else if (c < 704) { tab = t4; off = 672; sz = 32;  i = 4; sc = 5.656854249492380f; }
    else              { tab = t5; off = 704; sz = 64;  i = 5; sc = 8.0f; }
    int xi = x[s * 6 + i];
    e[idx] = tf32r(tab[xi * sz + (c - off)] * sc);
}

// Positional encoding: h stays fp32; hr = rounded copy for GEMM A
__global__ void posenc_kernel(float* __restrict__ h, float* __restrict__ hr)
{
    int idx = blockIdx.x * blockDim.x + threadIdx.x;
    if (idx >= SEQ * DM) return;
    int s = idx >> 9, c = idx & 511;
    int i2 = c >> 1;
    float freq = expf((float)(2 * i2) * (-9.210340371976184f / 512.0f));
    float ang = (float)s * freq;
    float val = h[idx] + ((c & 1) ? cosf(ang) : sinf(ang));
    h[idx] = val;
    hr[idx] = tf32r(val);
}

// ---------------------------------------------------------------------------
// tf32 tensor-core GEMM, cp.async 4-stage pipeline, BK=32, ldmatrix A-frags.
// A and B buffers are both pre-rounded tf32 bit patterns.
// ---------------------------------------------------------------------------
#define TBM 64
#define TBN 64
#define TBK 32
#define NSTAGE 4
#define SMEM_GEMM ((NSTAGE * TBM * 36 + NSTAGE * TBK * 72) * 4)
enum { EPI_NONE = 0, EPI_PHI = 1, EPI_GELU = 2, EPI_RESID = 3, EPI_ROUND = 4 };

struct GemmOp { const float* B; const float* bias; float* C; int epi; };

__global__ __launch_bounds__(128) void mma_gemm_kernel(
    const float* __restrict__ A, GemmOp op0, GemmOp op1, GemmOp op2,
    int M, int N, int K)
{
    GemmOp op = (blockIdx.z == 0) ? op0 : (blockIdx.z == 1) ? op1 : op2;

    extern __shared__ float gsm[];
    float (*As)[TBM][36] = (float (*)[TBM][36])gsm;
    float (*Bs)[TBK][72] = (float (*)[TBK][72])(gsm + NSTAGE * TBM * 36);

    int tid  = threadIdx.x;
    int lane = tid & 31, wid = tid >> 5;
    int wr = wid >> 1, wc = wid & 1;
    int rowBase = blockIdx.y * TBM;
    int colBase = blockIdx.x * TBN;

    int ar0 = tid >> 3;
    int ak4 = (tid & 7) * 4;
    int bk0 = tid >> 4;
    int bn4 = (tid & 15) * 4;

    const float* Abase = A + (size_t)rowBase * K;
    const float* Bbase = op.B + colBase;

    int nk = K / TBK;

#pragma unroll
    for (int s = 0; s < NSTAGE - 1; s++) {
#pragma unroll
        for (int i = 0; i < 4; i++) {
            int arw = ar0 + 16 * i;
            int bkr = bk0 + 8 * i;
            cp16((uint32_t)__cvta_generic_to_shared(&As[s][arw][ak4]),
                 Abase + (size_t)arw * K + s * TBK + ak4);
            cp16((uint32_t)__cvta_generic_to_shared(&Bs[s][bkr][bn4]),
                 Bbase + (size_t)(s * TBK + bkr) * N + bn4);
        }
        asm volatile("cp.async.commit_group;");
    }

    float acc[2][4][4];
#pragma unroll
    for (int i = 0; i < 2; i++)
#pragma unroll
        for (int j = 0; j < 4; j++)
#pragma unroll
            for (int r = 0; r < 4; r++) acc[i][j][r] = 0.f;

    int ar = lane >> 2;
    int ac = lane & 3;
    // ldmatrix lane addressing for A fragments
    int lrow = (lane & 7) + ((lane >> 3) & 1) * 8;   // row offset within 16-row tile
    int lcol = (lane >> 4) * 4;                       // 0 or 4

    for (int kc = 0; kc < nk; kc++) {
        asm volatile("cp.async.wait_group %0;" :: "n"(NSTAGE - 2));
        __syncthreads();

        int buf = kc & (NSTAGE - 1);
        const float (*Asb)[36] = As[buf];
        const float (*Bsb)[72] = Bs[buf];
        uint32_t abase = (uint32_t)__cvta_generic_to_shared(&Asb[0][0]);

#pragma unroll
        for (int ks = 0; ks < 4; ks++) {
            uint32_t af[2][4], bf[4][2];
#pragma unroll
            for (int tm = 0; tm < 2; tm++) {
                int mb = wr * 32 + tm * 16;
                uint32_t addr = abase + (uint32_t)(((mb + lrow) * 36 + ks * 8 + lcol) * 4);
                ldsm4(af[tm][0], af[tm][1], af[tm][2], af[tm][3], addr);
            }
#pragma unroll
            for (int tn = 0; tn < 4; tn++) {
                int nb = wc * 32 + tn * 8 + ar;
                bf[tn][0] = __float_as_uint(Bsb[ks * 8 + ac][nb]);
                bf[tn][1] = __float_as_uint(Bsb[ks * 8 + 4 + ac][nb]);
            }
#pragma unroll
            for (int tm = 0; tm < 2; tm++)
#pragma unroll
                for (int tn = 0; tn < 4; tn++)
                    mma_tf32(acc[tm][tn], af[tm], bf[tn]);
        }

        int nxt = kc + NSTAGE - 1;
        if (nxt < nk) {
            int st = nxt & (NSTAGE - 1);
#pragma unroll
            for (int i = 0; i < 4; i++) {
                int arw = ar0 + 16 * i;
                int bkr = bk0 + 8 * i;
                cp16((uint32_t)__cvta_generic_to_shared(&As[st][arw][ak4]),
                     Abase + (size_t)arw * K + nxt * TBK + ak4);
                cp16((uint32_t)__cvta_generic_to_shared(&Bs[st][bkr][bn4]),
                     Bbase + (size_t)(nxt * TBK + bkr) * N + bn4);
            }
        }
        asm volatile("cp.async.commit_group;");
    }

    // epilogue
#pragma unroll
    for (int tmL = 0; tmL < 2; tmL++) {
        int row0 = rowBase + wr * 32 + tmL * 16 + (lane >> 2);
#pragma unroll
        for (int tn = 0; tn < 4; tn++) {
            int col = colBase + wc * 32 + tn * 8 + (lane & 3) * 2;
            float2 bb = *(const float2*)(op.bias + col);
            float* C0 = op.C + (size_t)row0 * N + col;
            float* C1 = C0 + (size_t)8 * N;
            float v0 = acc[tmL][tn][0] + bb.x;
            float v1 = acc[tmL][tn][1] + bb.y;
            float v2 = acc[tmL][tn][2] + bb.x;
            float v3 = acc[tmL][tn][3] + bb.y;
            if (op.epi == EPI_PHI) {
                v0 = tf32r((v0 > 0.f) ? v0 + 1.0f : expf(v0));
                v1 = tf32r((v1 > 0.f) ? v1 + 1.0f : expf(v1));
                v2 = tf32r((v2 > 0.f) ? v2 + 1.0f : expf(v2));
                v3 = tf32r((v3 > 0.f) ? v3 + 1.0f : expf(v3));
            } else if (op.epi == EPI_GELU) {
                v0 = tf32r(0.5f * v0 * (1.0f + erff(v0 * 0.7071067811865475f)));
                v1 = tf32r(0.5f * v1 * (1.0f + erff(v1 * 0.7071067811865475f)));
                v2 = tf32r(0.5f * v2 * (1.0f + erff(v2 * 0.7071067811865475f)));
                v3 = tf32r(0.5f * v3 * (1.0f + erff(v3 * 0.7071067811865475f)));
            } else if (op.epi == EPI_RESID) {
                float2 o0 = *(const float2*)C0;
                float2 o1 = *(const float2*)C1;
                v0 += o0.x; v1 += o0.y; v2 += o1.x; v3 += o1.y;
            } else if (op.epi == EPI_ROUND) {
                v0 = tf32r(v0); v1 = tf32r(v1); v2 = tf32r(v2); v3 = tf32r(v3);
            }
            float2 r0 = {v0, v1}, r1 = {v2, v3};
            *(float2*)C0 = r0;
            *(float2*)C1 = r1;
        }
    }
}

// ---------------------------------------------------------------------------
// Fused attention A (q,k,v pre-rounded tf32):
//   S = mask(q k^T) (smem, rounded) + rowsums ; out_intra = S@v ; KV = k^T v
// ---------------------------------------------------------------------------
#define SMEM_ATTA ((3 * 128 * 68 + 128 * 132 + 128 * 4) * 4)

__global__ __launch_bounds__(256) void attn_a_kernel(
    const float* __restrict__ q, const float* __restrict__ k, const float* __restrict__ v,
    float* __restrict__ oi, float* __restrict__ rsg,
    float* __restrict__ KVch, float* __restrict__ Kch)
{
    extern __shared__ float sm[];
    float* qs  = sm;                        // [128][68]
    float* kn  = qs + 128 * 68;             // [128][68]
    float* vs  = kn + 128 * 68;             // [128][68]
    float* Ss  = vs + 128 * 68;             // [128][132] / later kT[64][132]
    float* rs2 = Ss + 128 * 132;            // [128][4]

    int c  = blockIdx.x;
    int hd = blockIdx.y;
    int tid = threadIdx.x;
    int lane = tid & 31, wid = tid >> 5;
    int wr = wid >> 2, wc = wid & 3;

    int lrow = (lane & 7) + ((lane >> 3) & 1) * 8;
    int lcol = (lane >> 4) * 4;
    // B-side (n-major) ldmatrix lane mapping
    int bnr = ((lane >> 4) * 8) + (lane & 7);   // n-row offset within 16-n supertile
    int bkc = ((lane >> 3) & 1) * 4;            // k offset 0/4

    uint32_t qsb = (uint32_t)__cvta_generic_to_shared(qs);
    uint32_t knb = (uint32_t)__cvta_generic_to_shared(kn);
    uint32_t ssb = (uint32_t)__cvta_generic_to_shared(Ss);

    {
        int r = tid >> 1;
        int dbase = (tid & 1) * 32;
        const float* gq = q + (size_t)(c * CHUNK + r) * DM + hd * DH + dbase;
        const float* gk = k + (size_t)(c * CHUNK + r) * DM + hd * DH + dbase;
        const float* gv = v + (size_t)(c * CHUNK + r) * DM + hd * DH + dbase;
#pragma unroll
        for (int j = 0; j < 8; j++) {
            int d = dbase + j * 4;
            *(float4*)&qs[r * 68 + d] = *(const float4*)(gq + j * 4);
            *(float4*)&kn[r * 68 + d] = *(const float4*)(gk + j * 4);
            *(float4*)&vs[r * 68 + d] = *(const float4*)(gv + j * 4);
        }
    }
    __syncthreads();

    // ---- S phase: warp tile 64x32, K=64 ----
    {
        float acc[4][4][4];
#pragma unroll
        for (int i = 0; i < 4; i++)
#pragma unroll
            for (int j = 0; j < 4; j++)
#pragma unroll
                for (int r = 0; r < 4; r++) acc[i][j][r] = 0.f;

#pragma unroll
        for (int ks = 0; ks < 8; ks++) {
            uint32_t af[4][4], bf[4][2];
#pragma unroll
            for (int tm = 0; tm < 4; tm++) {
                int mb = wr * 64 + tm * 16;
                ldsm4(af[tm][0], af[tm][1], af[tm][2], af[tm][3],
                      qsb + (uint32_t)(((mb + lrow) * 68 + ks * 8 + lcol) * 4));
            }
#pragma unroll
            for (int pair = 0; pair < 2; pair++) {
                int nb0 = wc * 32 + pair * 16;
                ldsm4(bf[pair * 2][0], bf[pair * 2][1], bf[pair * 2 + 1][0], bf[pair * 2 + 1][1],
                      knb + (uint32_t)(((nb0 + bnr) * 68 + ks * 8 + bkc) * 4));
            }
#pragma unroll
            for (int tm = 0; tm < 4; tm++)
#pragma unroll
                for (int tn = 0; tn < 4; tn++)
                    mma_tf32(acc[tm][tn], af[tm], bf[tn]);
        }

        // mask + rowsums + rounded store to smem
#pragma unroll
        for (int tm = 0; tm < 4; tm++) {
            int row0 = wr * 64 + tm * 16 + (lane >> 2);
            int row1 = row0 + 8;
            float p0 = 0.f, p1 = 0.f;
#pragma unroll
            for (int tn = 0; tn < 4; tn++) {
                int col = wc * 32 + tn * 8 + (lane & 3) * 2;
                float2 r0, r1;
                r0.x = (col     <= row0) ? acc[tm][tn][0] : 0.f;
                r0.y = (col + 1 <= row0) ? acc[tm][tn][1] : 0.f;
                r1.x = (col     <= row1) ? acc[tm][tn][2] : 0.f;
                r1.y = (col + 1 <= row1) ? acc[tm][tn][3] : 0.f;
                p0 += r0.x + r0.y;
                p1 += r1.x + r1.y;
                r0.x = tf32r(r0.x); r0.y = tf32r(r0.y);
                r1.x = tf32r(r1.x); r1.y = tf32r(r1.y);
                *(float2*)&Ss[row0 * 132 + col] = r0;
                *(float2*)&Ss[row1 * 132 + col] = r1;
            }
#pragma unroll
            for (int o = 1; o < 4; o <<= 1) {
                p0 += __shfl_xor_sync(0xffffffffu, p0, o);
                p1 += __shfl_xor_sync(0xffffffffu, p1, o);
            }
            if ((lane & 3) == 0) {
                rs2[row0 * 4 + wc] = p0;
                rs2[row1 * 4 + wc] = p1;
            }
        }
    }
    __syncthreads();

    if (tid < CHUNK) {
        rsg[(hd * NCHUNK + c) * CHUNK + tid] =
            rs2[tid * 4 + 0] + rs2[tid * 4 + 1] + rs2[tid * 4 + 2] + rs2[tid * 4 + 3];
    }

    // ---- out_intra = S @ v : warp tile 64x16, K=128 ----
    {
        float acc[4][2][4];
#pragma unroll
        for (int i = 0; i < 4; i++)
#pragma unroll
            for (int j = 0; j < 2; j++)
#pragma unroll
                for (int r = 0; r < 4; r++) acc[i][j][r] = 0.f;

#pragma unroll
        for (int ks = 0; ks < 16; ks++) {
            uint32_t af[4][4], bf[2][2];
#pragma unroll
            for (int tm = 0; tm < 4; tm++) {
                int mb = wr * 64 + tm * 16;
                ldsm4(af[tm][0], af[tm][1], af[tm][2], af[tm][3],
                      ssb + (uint32_t)(((mb + lrow) * 132 + ks * 8 + lcol) * 4));
            }
#pragma unroll
            for (int tn = 0; tn < 2; tn++) {
                int nb = wc * 16 + tn * 8 + (lane >> 2);
                bf[tn][0] = __float_as_uint(vs[(ks * 8 + (lane & 3)) * 68 + nb]);
                bf[tn][1] = __float_as_uint(vs[(ks * 8 + 4 + (lane & 3)) * 68 + nb]);
            }
#pragma unroll
            for (int tm = 0; tm < 4; tm++)
#pragma unroll
                for (int tn = 0; tn < 2; tn++)
                    mma_tf32(acc[tm][tn], af[tm], bf[tn]);
        }

#pragma unroll
        for (int tm = 0; tm < 4; tm++) {
            int s0 = wr * 64 + tm * 16 + (lane >> 2);
            int s1 = s0 + 8;
#pragma unroll
            for (int tn = 0; tn < 2; tn++) {
                int e = wc * 16 + tn * 8 + (lane & 3) * 2;
                float2 r0 = {acc[tm][tn][0], acc[tm][tn][1]};
                float2 r1 = {acc[tm][tn][2], acc[tm][tn][3]};
                *(float2*)&oi[(size_t)(c * CHUNK + s0) * DM + hd * DH + e] = r0;
                *(float2*)&oi[(size_t)(c * CHUNK + s1) * DM + hd * DH + e] = r1;
            }
        }
    }
    __syncthreads();

    // ---- build kT[64][132] into Ss region (values already tf32) ----
    for (int idx = tid; idx < CHUNK * DH; idx += 256) {
        int r = idx >> 6, d = idx & 63;
        Ss[d * 132 + r] = kn[r * 68 + d];
    }
    __syncthreads();

    // ---- KV = k^T v : warp tile 32x16, K=128 ----
    {
        float acc[2][2][4];
#pragma unroll
        for (int i = 0; i < 2; i++)
#pragma unroll
            for (int j = 0; j < 2; j++)
#pragma unroll
                for (int r = 0; r < 4; r++) acc[i][j][r] = 0.f;

#pragma unroll
        for (int ks = 0; ks < 16; ks++) {
            uint32_t af[2][4], bf[2][2];
#pragma unroll
            for (int tm = 0; tm < 2; tm++) {
                int mb = wr * 32 + tm * 16;
                ldsm4(af[tm][0], af[tm][1], af[tm][2], af[tm][3],
                      ssb + (uint32_t)(((mb + lrow) * 132 + ks * 8 + lcol) * 4));
            }
#pragma unroll
            for (int tn = 0; tn < 2; tn++) {
                int nb = wc * 16 + tn * 8 + (lane >> 2);
                bf[tn][0] = __float_as_uint(vs[(ks * 8 + (lane & 3)) * 68 + nb]);
                bf[tn][1] = __float_as_uint(vs[(ks * 8 + 4 + (lane & 3)) * 68 + nb]);
            }
#pragma unroll
            for (int tm = 0; tm < 2; tm++)
#pragma unroll
                for (int tn = 0; tn < 2; tn++)
                    mma_tf32(acc[tm][tn], af[tm], bf[tn]);
        }

        float* KVo = KVch + (size_t)(hd * NCHUNK + c) * (DH * DH);
#pragma unroll
        for (int tm = 0; tm < 2; tm++) {
            int d0 = wr * 32 + tm * 16 + (lane >> 2);
            int d1 = d0 + 8;
#pragma unroll
            for (int tn = 0; tn < 2; tn++) {
                int e = wc * 16 + tn * 8 + (lane & 3) * 2;
                float2 r0 = {acc[tm][tn][0], acc[tm][tn][1]};
                float2 r1 = {acc[tm][tn][2], acc[tm][tn][3]};
                *(float2*)&KVo[d0 * DH + e] = r0;
                *(float2*)&KVo[d1 * DH + e] = r1;
            }
        }
    }

    if (tid < DH) {
        float s = 0.f;
        for (int t = 0; t < CHUNK; t++) s += kn[t * 68 + tid];
        Kch[(hd * NCHUNK + c) * DH + tid] = s;
    }
}

// ---------------------------------------------------------------------------
// Fused attention B: inline scan + z + out = z * (oi + q @ kvcarry)
// ---------------------------------------------------------------------------
#define SMEM_ATTB ((128 * 68 + 64 * 68 + 64 + 128) * 4)

__global__ __launch_bounds__(256) void attn_b_kernel(
    const float* __restrict__ q, const float* __restrict__ oi, const float* __restrict__ rsg,
    const float* __restrict__ KVch, const float* __restrict__ Kch, float* __restrict__ out)
{
    extern __shared__ float sm[];
    float* qs = sm;                 // [128][68]
    float* kv = qs + 128 * 68;      // [64][68]
    float* kc = kv + 64 * 68;       // [64]
    float* zz = kc + 64;            // [128]

    int c  = blockIdx.x;
    int hd = blockIdx.y;
    int tid = threadIdx.x;
    int lane = tid & 31, wid = tid >> 5;
    int wr = wid >> 2, wc = wid & 3;

    int lrow = (lane & 7) + ((lane >> 3) & 1) * 8;
    int lcol = (lane >> 4) * 4;
    uint32_t qsb = (uint32_t)__cvta_generic_to_shared(qs);

    {
        int r = tid >> 1;
        int eb = (tid & 1) * 32;
        const float* gq = q + (size_t)(c * CHUNK + r) * DM + hd * DH + eb;
#pragma unroll
        for (int j = 0; j < 8; j++)
            *(float4*)&qs[r * 68 + eb + j * 4] = *(const float4*)(gq + j * 4);
    }
    for (int i = tid; i < DH * DH; i += 256) {
        float s = 0.f;
        for (int cc = 0; cc < c; cc++)
            s += KVch[(size_t)(hd * NCHUNK + cc) * (DH * DH) + i];
        kv[(i >> 6) * 68 + (i & 63)] = tf32r(s);
    }
    if (tid < DH) {
        float s = 0.f;
        for (int cc = 0; cc < c; cc++)
            s += Kch[(hd * NCHUNK + cc) * DH + tid];
        kc[tid] = s;
    }
    __syncthreads();

    if (tid < CHUNK) {
        float zr = rsg[(hd * NCHUNK + c) * CHUNK + tid];
        for (int d = 0; d < DH; d++) zr = fmaf(qs[tid * 68 + d], kc[d], zr);
        zz[tid] = 1.0f / (zr + EPS_ATTN);
    }
    __syncthreads();

    float acc[4][2][4];
#pragma unroll
    for (int i = 0; i < 4; i++)
#pragma unroll
        for (int j = 0; j < 2; j++)
#pragma unroll
            for (int r = 0; r < 4; r++) acc[i][j][r] = 0.f;

#pragma unroll
    for (int ks = 0; ks < 8; ks++) {
        uint32_t af[4][4], bf[2][2];
#pragma unroll
        for (int tm = 0; tm < 4; tm++) {
            int mb = wr * 64 + tm * 16;
            ldsm4(af[tm][0], af[tm][1], af[tm][2], af[tm][3],
                  qsb + (uint32_t)(((mb + lrow) * 68 + ks * 8 + lcol) * 4));
        }
#pragma unroll
        for (int tn = 0; tn < 2; tn++) {
            int nb = wc * 16 + tn * 8 + (lane >> 2);
            bf[tn][0] = __float_as_uint(kv[(ks * 8 + (lane & 3)) * 68 + nb]);
            bf[tn][1] = __float_as_uint(kv[(ks * 8 + 4 + (lane & 3)) * 68 + nb]);
        }
#pragma unroll
        for (int tm = 0; tm < 4; tm++)
#pragma unroll
            for (int tn = 0; tn < 2; tn++)
                mma_tf32(acc[tm][tn], af[tm], bf[tn]);
    }

#pragma unroll
    for (int tm = 0; tm < 4; tm++) {
        int s0 = wr * 64 + tm * 16 + (lane >> 2);
        int s1 = s0 + 8;
        float z0 = zz[s0], z1 = zz[s1];
#pragma unroll
        for (int tn = 0; tn < 2; tn++) {
            int e = wc * 16 + tn * 8 + (lane & 3) * 2;
            size_t o0 = (size_t)(c * CHUNK + s0) * DM + hd * DH + e;
            size_t o1 = (size_t)(c * CHUNK + s1) * DM + hd * DH + e;
            float2 i0 = *(const float2*)&oi[o0];
            float2 i1 = *(const float2*)&oi[o1];
            float2 r0 = {tf32r(z0 * (i0.x + acc[tm][tn][0])), tf32r(z0 * (i0.y + acc[tm][tn][1]))};
            float2 r1 = {tf32r(z1 * (i1.x + acc[tm][tn][2])), tf32r(z1 * (i1.y + acc[tm][tn][3]))};
            *(float2*)&out[o0] = r0;
            *(float2*)&out[o1] = r1;
        }
    }
}

// ---------------------------------------------------------------------------
// LayerNorm: warp per row, 8 rows/block; dual output (fp32 + rounded mirror)
// ---------------------------------------------------------------------------
__global__ __launch_bounds__(256) void ln_kernel(
    const float* __restrict__ src, float* __restrict__ dst, float* __restrict__ dstr,
    const float* __restrict__ g, const float* __restrict__ b)
{
    int row = blockIdx.x * 8 + (threadIdx.x >> 5);
    int lane = threadIdx.x & 31;
    const float* sr = src + (size_t)row * DM + lane * 16;
    float4 v[4];
    float sum = 0.f, sq = 0.f;
#pragma unroll
    for (int i = 0; i < 4; i++) {
        v[i] = *(const float4*)(sr + i * 4);
        sum += v[i].x + v[i].y + v[i].z + v[i].w;
        sq  += v[i].x * v[i].x + v[i].y * v[i].y + v[i].z * v[i].z + v[i].w * v[i].w;
    }
#pragma unroll
    for (int o = 16; o > 0; o >>= 1) {
        sum += __shfl_xor_sync(0xffffffffu, sum, o);
        sq  += __shfl_xor_sync(0xffffffffu, sq,  o);
    }
    float mean = sum * (1.0f / DM);
    float var  = sq * (1.0f / DM) - mean * mean;
    float r = rsqrtf(var + EPS_LN);
    float* dr = dst + (size_t)row * DM + lane * 16;
#pragma unroll
    for (int i = 0; i < 4; i++) {
        float4 gg = *(const float4*)(g + lane * 16 + i * 4);
        float4 bb = *(const float4*)(b + lane * 16 + i * 4);
        float4 o;
        o.x = (v[i].x - mean) * r * gg.x + bb.x;
        o.y = (v[i].y - mean) * r * gg.y + bb.y;
        o.z = (v[i].z - mean) * r * gg.z + bb.z;
        o.w = (v[i].w - mean) * r * gg.w + bb.w;
        *(float4*)(dr + i * 4) = o;
        if (dstr) {
            float4 q;
            q.x = tf32r(o.x); q.y = tf32r(o.y); q.z = tf32r(o.z); q.w = tf32r(o.w);
            *(float4*)(dstr + (size_t)row * DM + lane * 16 + i * 4) = q;
        }
    }
}

// ---------------------------------------------------------------------------
// Emotion projection
// ---------------------------------------------------------------------------
__global__ __launch_bounds__(256) void emo_kernel(
    const float* __restrict__ hn, const float* __restrict__ W,
    const float* __restrict__ bias, float* __restrict__ out)
{
    int s = blockIdx.x;
    int w = threadIdx.x >> 5, lane = threadIdx.x & 31;
    float acc = 0.f;
    const float* hr = hn + (size_t)s * DM;
    for (int d = lane; d < DM; d += 32)
        acc = fmaf(hr[d], W[d * 8 + w], acc);
#pragma unroll
    for (int o = 16; o > 0; o >>= 1) acc += __shfl_xor_sync(0xffffffffu, acc, o);
    if (lane == 0) out[s * 8 + w] = acc + bias[w];
}

// ---------------------------------------------------------------------------
// Host launch
// ---------------------------------------------------------------------------
template <typename T>
static float* symptr(T& sym)
{
    void* p = nullptr;
    cudaGetSymbolAddress(&p, sym);
    return (float*)p;
}

extern "C" void kernel_launch(void* const* d_in, const int* in_sizes, int n_in,
                              void* d_out, int out_size)
{
    const int*   x        = (const int*)  d_in[0];
    const float* emb_bar  = (const float*)d_in[1];
    const float* emb_pos  = (const float*)d_in[2];
    const float* emb_pit  = (const float*)d_in[3];
    const float* emb_dur  = (const float*)d_in[4];
    const float* emb_typ  = (const float*)d_in[5];
    const float* emb_emo  = (const float*)d_in[6];
    const float* in_w     = (const float*)d_in[7];
    const float* in_b     = (const float*)d_in[8];
    const float* wq       = (const float*)d_in[9];
    const float* bq       = (const float*)d_in[10];
    const float* wk       = (const float*)d_in[11];
    const float* bk       = (const float*)d_in[12];
    const float* wv       = (const float*)d_in[13];
    const float* bv       = (const float*)d_in[14];
    const float* wo       = (const float*)d_in[15];
    const float* bo       = (const float*)d_in[16];
    const float* ln1_g    = (const float*)d_in[17];
    const float* ln1_b    = (const float*)d_in[18];
    const float* w1       = (const float*)d_in[19];
    const float* b1       = (const float*)d_in[20];
    const float* w2       = (const float*)d_in[21];
    const float* b2       = (const float*)d_in[22];
    const float* ln2_g    = (const float*)d_in[23];
    const float* ln2_b    = (const float*)d_in[24];
    const float* lnf_g    = (const float*)d_in[25];
    const float* lnf_b    = (const float*)d_in[26];
    const float* proj_w   = (const float*)d_in[27];
    const float* proj_b   = (const float*)d_in[28];

    float* embs = symptr(g_embs);
    float* h    = symptr(g_h);
    float* hr   = symptr(g_hr);
    float* q    = symptr(g_q);
    float* k    = symptr(g_k);
    float* v    = symptr(g_v);
    float* attn = symptr(g_attn);
    float* oi   = symptr(g_oi);
    float* ff   = symptr(g_ff);
    float* KVch = symptr(g_KVch);
    float* Kch  = symptr(g_Kch);
    float* rsg  = symptr(g_rs);
    float* hn   = symptr(g_hn);

    float* wq_r  = symptr(g_wq_r);
    float* wk_r  = symptr(g_wk_r);
    float* wv_r  = symptr(g_wv_r);
    float* wo_r  = symptr(g_wo_r);
    float* w1_r  = symptr(g_w1_r);
    float* w2_r  = symptr(g_w2_r);
    float* inw_r = symptr(g_inw_r);

    cudaFuncSetAttribute(mma_gemm_kernel, cudaFuncAttributeMaxDynamicSharedMemorySize, SMEM_GEMM);
    cudaFuncSetAttribute(attn_a_kernel,   cudaFuncAttributeMaxDynamicSharedMemorySize, SMEM_ATTA);
    cudaFuncSetAttribute(attn_b_kernel,   cudaFuncAttributeMaxDynamicSharedMemorySize, SMEM_ATTB);

    // --- weight pre-rounding to tf32 ---
    {
        const int T = 256;
        int n4;
        n4 = DEMB * DM / 4;
        round_tf32_kernel<<<(n4 + T - 1) / T, T>>>((const float4*)in_w, (float4*)inw_r, n4);
        n4 = NLAYER * DM * DM / 4;
        round_tf32_kernel<<<(n4 + T - 1) / T, T>>>((const float4*)wq, (float4*)wq_r, n4);
        round_tf32_kernel<<<(n4 + T - 1) / T, T>>>((const float4*)wk, (float4*)wk_r, n4);
        round_tf32_kernel<<<(n4 + T - 1) / T, T>>>((const float4*)wv, (float4*)wv_r, n4);
        round_tf32_kernel<<<(n4 + T - 1) / T, T>>>((const float4*)wo, (float4*)wo_r, n4);
        n4 = NLAYER * DM * DFF / 4;
        round_tf32_kernel<<<(n4 + T - 1) / T, T>>>((const float4*)w1, (float4*)w1_r, n4);
        round_tf32_kernel<<<(n4 + T - 1) / T, T>>>((const float4*)w2, (float4*)w2_r, n4);
    }

    // Embedding + input projection + positional encoding
    embed_kernel<<<(SEQ * DEMB + 255) / 256, 256>>>(x, emb_bar, emb_pos, emb_pit,
                                                    emb_dur, emb_typ, emb_emo, embs);
    {
        GemmOp op{inw_r, in_b, h, EPI_NONE};
        mma_gemm_kernel<<<dim3(DM / TBN, SEQ / TBM, 1), 128, SMEM_GEMM>>>(embs, op, op, op, SEQ, DM, DEMB);
    }
    posenc_kernel<<<(SEQ * DM + 255) / 256, 256>>>(h, hr);

    for (int l = 0; l < NLAYER; l++) {
        const float* wq_l = wq_r + (size_t)l * DM * DM;
        const float* wk_l = wk_r + (size_t)l * DM * DM;
        const float* wv_l = wv_r + (size_t)l * DM * DM;
        const float* wo_l = wo_r + (size_t)l * DM * DM;
        const float* w1_l = w1_r + (size_t)l * DM * DFF;
        const float* w2_l = w2_r + (size_t)l * DFF * DM;

        GemmOp oq{wq_l, bq + l * DM, q, EPI_PHI};
        GemmOp ok{wk_l, bk + l * DM, k, EPI_PHI};
        GemmOp ov{wv_l, bv + l * DM, v, EPI_ROUND};
        mma_gemm_kernel<<<dim3(DM / TBN, SEQ / TBM, 3), 128, SMEM_GEMM>>>(hr, oq, ok, ov, SEQ, DM, DM);

        attn_a_kernel<<<dim3(NCHUNK, NHEAD), 256, SMEM_ATTA>>>(q, k, v, oi, rsg, KVch, Kch);
        attn_b_kernel<<<dim3(NCHUNK, NHEAD), 256, SMEM_ATTB>>>(q, oi, rsg, KVch, Kch, attn);

        GemmOp oo{wo_l, bo + l * DM, h, EPI_RESID};
        mma_gemm_kernel<<<dim3(DM / TBN, SEQ / TBM, 1), 128, SMEM_GEMM>>>(attn, oo, oo, oo, SEQ, DM, DM);
        ln_kernel<<<SEQ / 8, 256>>>(h, h, hr, ln1_g + l * DM, ln1_b + l * DM);

        GemmOp of1{w1_l, b1 + l * DFF, ff, EPI_GELU};
        mma_gemm_kernel<<<dim3(DFF / TBN, SEQ / TBM, 1), 128, SMEM_GEMM>>>(hr, of1, of1, of1, SEQ, DFF, DM);
        GemmOp of2{w2_l, b2 + l * DM, h, EPI_RESID};
        mma_gemm_kernel<<<dim3(DM / TBN, SEQ / TBM, 1), 128, SMEM_GEMM>>>(ff, of2, of2, of2, SEQ, DM, DFF);
        ln_kernel<<<SEQ / 8, 256>>>(h, h, hr, ln2_g + l * DM, ln2_b + l * DM);
    }

    // Final norm + outputs
    float* o = (float*)d_out;
    float* hdst;
    float* edst;
    const int H_ELEMS = SEQ * DM;
    const int E_ELEMS = SEQ * 8;
    if (out_size >= H_ELEMS + E_ELEMS)      { hdst = o;  edst = o + H_ELEMS; }
    else if (out_size >= H_ELEMS)           { hdst = o;  edst = hn; }
    else                                    { hdst = hn; edst = o; }

    ln_kernel<<<SEQ / 8, 256>>>(h, hdst, nullptr, lnf_g, lnf_b);
    emo_kernel<<<SEQ, 256>>>(hdst, proj_w, proj_b, edst);
}